// round 12
// baseline (speedup 1.0000x reference)
#include <cuda_runtime.h>

// Problem shape
#define B    4
#define T    8192
#define D    512
#define CH   8                 // time steps per chunk (per block)
#define NC   (T / CH)          // 1024 chunks per sequence
#define TPB  128               // threads per block
#define NDG  2                 // D-groups (channel halves) per chunk
#define DG   (D / NDG)         // 256 channels per block
#define LBW  4                 // lookback window

// Flag states
#define FLG_NONE 0
#define FLG_AGG  1
#define FLG_PREF 2

// Scratch (device globals; zero-initialized at module load).
__device__ float2 g_aggv [B * NC * D];            // per-chunk (a, h_local_end)
__device__ float  g_prefh[B * NC * D];            // per-chunk inclusive-prefix h
__device__ int    g_flag [B * NDG * NC * TPB];    // per-(b, dgroup, chunk, thread)

__device__ __forceinline__ float tanha(float x) {
    float y;
    asm("tanh.approx.f32 %0, %1;" : "=f"(y) : "f"(x));
    return y;
}
__device__ __forceinline__ float sigm(float x) {
    return fmaf(tanha(0.5f * x), 0.5f, 0.5f);
}
__device__ __forceinline__ void st_release(int* p, int v) {
    asm volatile("st.release.gpu.global.b32 [%0], %1;" :: "l"(p), "r"(v) : "memory");
}
__device__ __forceinline__ int ld_acquire(const int* p) {
    int v;
    asm volatile("ld.acquire.gpu.global.b32 %0, [%1];" : "=r"(v) : "l"(p) : "memory");
    return v;
}

__global__ void __launch_bounds__(TPB, 7)
scan_onepass(const float* __restrict__ x, float* __restrict__ out) {
    const int c   = blockIdx.x;          // chunk (predecessors have lower bid)
    const int dg  = blockIdx.y;          // channel half
    const int b   = blockIdx.z;          // batch
    const int tid = threadIdx.x;
    const int ch  = dg * DG + tid * 2;   // absolute channel base (owns 2)

    const float* base  = x   + ((size_t)b * T + (size_t)c * CH) * (3 * D) + ch;
    float*       obase = out + ((size_t)b * T + (size_t)c * CH) * D + ch;

    // ---- Phase 1a: batch the 16 V/G loads (burst #1) -----------------------
    float2 V[CH], G[CH];
#pragma unroll
    for (int t = 0; t < CH; ++t) {
        V[t] = __ldcs((const float2*)(base + (size_t)t * (3 * D)));
        G[t] = __ldcs((const float2*)(base + (size_t)t * (3 * D) + D));
    }

    // ---- Phase 1b: local chunk scan; F and W stay in REGISTERS -------------
    float2 F[CH], W[CH];
    float a0 = 1.f, a1 = 1.f;
    float h0 = 0.f, h1 = 0.f;
#pragma unroll
    for (int t = 0; t < CH; ++t) {
        float i0 = sigm(G[t].x), i1 = sigm(G[t].y);
        float f0 = 1.f - i0,     f1 = 1.f - i1;
        float w0 = i0 * tanha(V[t].x), w1 = i1 * tanha(V[t].y);

        F[t] = make_float2(f0, f1);
        W[t] = make_float2(w0, w1);

        a0 *= f0; a1 *= f1;
        h0 = fmaf(f0, h0, w0);
        h1 = fmaf(f1, h1, w1);
    }

    const size_t sidx  = ((size_t)b * NC + c) * D + ch;      // value index (2 ch)
    const int    fbase = ((b * NDG + dg) * NC) * TPB + tid;  // flag index helper

    float He0 = 0.f, He1 = 0.f;          // exclusive prefix h

    if (c == 0) {
        __stcg((float2*)&g_prefh[sidx], make_float2(h0, h1));
        st_release(&g_flag[fbase + 0 * TPB], FLG_PREF);
    } else {
        __stcg((float4*)&g_aggv[sidx], make_float4(a0, h0, a1, h1));
        st_release(&g_flag[fbase + c * TPB], FLG_AGG);

        // ---- Phase 2: decoupled lookback (per-thread, no barriers) ---------
        float As0 = 1.f, As1 = 1.f;
        float Bs0 = 0.f, Bs1 = 0.f;

        int p = c - 1;
        bool done = false;
        while (!done) {
            const int w = (p + 1 < LBW) ? (p + 1) : LBW;

            int fl[LBW];
            for (;;) {
                bool all = true;
#pragma unroll
                for (int k = 0; k < LBW; ++k) {
                    if (k < w) {
                        fl[k] = ld_acquire(&g_flag[fbase + (p - k) * TPB]);
                        all &= (fl[k] != FLG_NONE);
                    }
                }
                if (all) break;
            }

            int kpref = -1;
#pragma unroll
            for (int k = 0; k < LBW; ++k)
                if (k < w && kpref < 0 && fl[k] == FLG_PREF) kpref = k;
            const int kend = (kpref >= 0) ? kpref : (w - 1);

            for (int k = 0; k <= kend; ++k) {
                const size_t vb = ((size_t)b * NC + (p - k)) * D + ch;
                if (k == kpref) {
                    float2 pv = __ldcg((const float2*)&g_prefh[vb]);
                    He0 = fmaf(As0, pv.x, Bs0);
                    He1 = fmaf(As1, pv.y, Bs1);
                    done = true;
                    break;
                } else {
                    float4 q = __ldcg((const float4*)&g_aggv[vb]);
                    Bs0 = fmaf(As0, q.y, Bs0); As0 *= q.x;
                    Bs1 = fmaf(As1, q.w, Bs1); As1 *= q.z;
                }
            }
            if (!done) {
                p -= w;
                if (p < 0) {
                    He0 = Bs0; He1 = Bs1;
                    done = true;
                }
            }
        }

        __stcg((float2*)&g_prefh[sidx],
               make_float2(fmaf(a0, He0, h0), fmaf(a1, He1, h1)));
        st_release(&g_flag[fbase + c * TPB], FLG_PREF);
    }

    // ---- Phase 3: GO burst (#2), replay from registers, emit ---------------
    float2 GO[CH];
#pragma unroll
    for (int t = 0; t < CH; ++t)
        GO[t] = __ldcs((const float2*)(base + (size_t)t * (3 * D) + 2 * D));

    float k0 = He0, k1 = He1;
#pragma unroll
    for (int t = 0; t < CH; ++t) {
        k0 = fmaf(F[t].x, k0, W[t].x);
        k1 = fmaf(F[t].y, k1, W[t].y);

        float2 o2;
        o2.x = tanha(k0) * sigm(GO[t].x);
        o2.y = tanha(k1) * sigm(GO[t].y);
        __stcs((float2*)(obase + (size_t)t * D), o2);
    }
}

extern "C" void kernel_launch(void* const* d_in, const int* in_sizes, int n_in,
                              void* d_out, int out_size) {
    const float* x = (const float*)d_in[0];
    float* out = (float*)d_out;

    dim3 grid(NC, NDG, B);   // 1024 x 2 x 4 = 8192 blocks
    scan_onepass<<<grid, TPB>>>(x, out);
}

// round 13
// speedup vs baseline: 1.0201x; 1.0201x over previous
#include <cuda_runtime.h>

// Problem shape
#define B    4
#define T    8192
#define D    512
#define CH   16                // time steps per chunk (per block)
#define SUB  8                 // sub-chunk (register tile)
#define NC   (T / CH)          // 512 chunks per sequence
#define TPB  128               // threads per block
#define NDG  2                 // D-groups (channel halves) per chunk
#define DG   (D / NDG)         // 256 channels per block
#define LBW  4                 // lookback window

// Flag states
#define FLG_NONE 0
#define FLG_AGG  1
#define FLG_PREF 2

// Scratch (device globals; zero-initialized at module load).
__device__ float2 g_aggv [B * NC * D];            // per-chunk (a, h_local_end)
__device__ float  g_prefh[B * NC * D];            // per-chunk inclusive-prefix h
__device__ int    g_flag [B * NDG * NC * TPB];    // per-(b, dgroup, chunk, thread)

__device__ __forceinline__ float tanha(float x) {
    float y;
    asm("tanh.approx.f32 %0, %1;" : "=f"(y) : "f"(x));
    return y;
}
__device__ __forceinline__ float sigm(float x) {
    return fmaf(tanha(0.5f * x), 0.5f, 0.5f);
}
__device__ __forceinline__ void st_release(int* p, int v) {
    asm volatile("st.release.gpu.global.b32 [%0], %1;" :: "l"(p), "r"(v) : "memory");
}
__device__ __forceinline__ int ld_acquire(const int* p) {
    int v;
    asm volatile("ld.acquire.gpu.global.b32 %0, [%1];" : "=r"(v) : "l"(p) : "memory");
    return v;
}

__global__ void __launch_bounds__(TPB, 7)
scan_onepass(const float* __restrict__ x, float* __restrict__ out) {
    // Per-thread-private stash: (f0, f1, w0, w1) per (t, thread). 32 KB.
    __shared__ float4 sm_fw[CH * TPB];

    const int c   = blockIdx.x;          // chunk (predecessors have lower bid)
    const int dg  = blockIdx.y;          // channel half
    const int b   = blockIdx.z;          // batch
    const int tid = threadIdx.x;
    const int ch  = dg * DG + tid * 2;   // absolute channel base (owns 2)

    const float* base  = x   + ((size_t)b * T + (size_t)c * CH) * (3 * D) + ch;
    float*       obase = out + ((size_t)b * T + (size_t)c * CH) * D + ch;

    // ---- Phase 1: two sub-chunks of SUB steps: burst-load, compute, stash --
    float a0 = 1.f, a1 = 1.f;
    float h0 = 0.f, h1 = 0.f;

#pragma unroll
    for (int s = 0; s < CH / SUB; ++s) {
        float2 V[SUB], G[SUB];
#pragma unroll
        for (int t = 0; t < SUB; ++t) {
            const size_t row = (size_t)(s * SUB + t) * (3 * D);
            V[t] = __ldcs((const float2*)(base + row));
            G[t] = __ldcs((const float2*)(base + row + D));
        }
#pragma unroll
        for (int t = 0; t < SUB; ++t) {
            float i0 = sigm(G[t].x), i1 = sigm(G[t].y);
            float f0 = 1.f - i0,     f1 = 1.f - i1;
            float w0 = i0 * tanha(V[t].x), w1 = i1 * tanha(V[t].y);

            sm_fw[(s * SUB + t) * TPB + tid] = make_float4(f0, f1, w0, w1);

            a0 *= f0; a1 *= f1;
            h0 = fmaf(f0, h0, w0);
            h1 = fmaf(f1, h1, w1);
        }
    }

    const size_t sidx  = ((size_t)b * NC + c) * D + ch;      // value index (2 ch)
    const int    fbase = ((b * NDG + dg) * NC) * TPB + tid;  // flag index helper

    float He0 = 0.f, He1 = 0.f;          // exclusive prefix h

    if (c == 0) {
        __stcg((float2*)&g_prefh[sidx], make_float2(h0, h1));
        st_release(&g_flag[fbase + 0 * TPB], FLG_PREF);
    } else {
        __stcg((float4*)&g_aggv[sidx], make_float4(a0, h0, a1, h1));
        st_release(&g_flag[fbase + c * TPB], FLG_AGG);

        // ---- Phase 2: decoupled lookback (per-thread, no barriers) ---------
        float As0 = 1.f, As1 = 1.f;
        float Bs0 = 0.f, Bs1 = 0.f;

        int p = c - 1;
        bool done = false;
        while (!done) {
            const int w = (p + 1 < LBW) ? (p + 1) : LBW;

            int fl[LBW];
            for (;;) {
                bool all = true;
#pragma unroll
                for (int k = 0; k < LBW; ++k) {
                    if (k < w) {
                        fl[k] = ld_acquire(&g_flag[fbase + (p - k) * TPB]);
                        all &= (fl[k] != FLG_NONE);
                    }
                }
                if (all) break;
            }

            int kpref = -1;
#pragma unroll
            for (int k = 0; k < LBW; ++k)
                if (k < w && kpref < 0 && fl[k] == FLG_PREF) kpref = k;
            const int kend = (kpref >= 0) ? kpref : (w - 1);

            for (int k = 0; k <= kend; ++k) {
                const size_t vb = ((size_t)b * NC + (p - k)) * D + ch;
                if (k == kpref) {
                    float2 pv = __ldcg((const float2*)&g_prefh[vb]);
                    He0 = fmaf(As0, pv.x, Bs0);
                    He1 = fmaf(As1, pv.y, Bs1);
                    done = true;
                    break;
                } else {
                    float4 q = __ldcg((const float4*)&g_aggv[vb]);
                    Bs0 = fmaf(As0, q.y, Bs0); As0 *= q.x;
                    Bs1 = fmaf(As1, q.w, Bs1); As1 *= q.z;
                }
            }
            if (!done) {
                p -= w;
                if (p < 0) {
                    He0 = Bs0; He1 = Bs1;
                    done = true;
                }
            }
        }

        __stcg((float2*)&g_prefh[sidx],
               make_float2(fmaf(a0, He0, h0), fmaf(a1, He1, h1)));
        st_release(&g_flag[fbase + c * TPB], FLG_PREF);
    }

    // ---- Phase 3: two GO bursts + replay from stash, emit -------------------
    float k0 = He0, k1 = He1;
#pragma unroll
    for (int s = 0; s < CH / SUB; ++s) {
        float2 GO[SUB];
#pragma unroll
        for (int t = 0; t < SUB; ++t)
            GO[t] = __ldcs((const float2*)(base + (size_t)(s * SUB + t) * (3 * D) + 2 * D));

#pragma unroll
        for (int t = 0; t < SUB; ++t) {
            const float4 fw = sm_fw[(s * SUB + t) * TPB + tid];

            k0 = fmaf(fw.x, k0, fw.z);
            k1 = fmaf(fw.y, k1, fw.w);

            float2 o2;
            o2.x = tanha(k0) * sigm(GO[t].x);
            o2.y = tanha(k1) * sigm(GO[t].y);
            __stcs((float2*)(obase + (size_t)(s * SUB + t) * D), o2);
        }
    }
}

extern "C" void kernel_launch(void* const* d_in, const int* in_sizes, int n_in,
                              void* d_out, int out_size) {
    const float* x = (const float*)d_in[0];
    float* out = (float*)d_out;

    dim3 grid(NC, NDG, B);   // 512 x 2 x 4 = 4096 blocks
    scan_onepass<<<grid, TPB>>>(x, out);
}

// round 14
// speedup vs baseline: 1.5302x; 1.5000x over previous
#include <cuda_runtime.h>

// Problem shape
#define B    4
#define T    8192
#define D    512
#define CH   32                // time steps per chunk (per block)
#define S    4                 // subtile steps (pipeline stage)
#define NS   (CH / S)          // 8 subtiles
#define NC   (T / CH)          // 256 chunks per sequence
#define TPB  128               // threads per block
#define NDG  2                 // D-groups (channel halves) per chunk
#define DG   (D / NDG)         // 256 channels per block

// Flag states
#define FLG_NONE 0
#define FLG_PREF 2

// Scratch (device globals; zero-initialized at module load).
__device__ float g_prefh[B * NC * D];             // per-chunk inclusive-prefix h
__device__ int   g_flag [B * NDG * NC * TPB];     // per-(b, dgroup, chunk, thread)

__device__ __forceinline__ float tanha(float x) {
    float y;
    asm("tanh.approx.f32 %0, %1;" : "=f"(y) : "f"(x));
    return y;
}
__device__ __forceinline__ float sigm(float x) {
    return fmaf(tanha(0.5f * x), 0.5f, 0.5f);
}
__device__ __forceinline__ void st_release(int* p, int v) {
    asm volatile("st.release.gpu.global.b32 [%0], %1;" :: "l"(p), "r"(v) : "memory");
}
__device__ __forceinline__ int ld_acquire(const int* p) {
    int v;
    asm volatile("ld.acquire.gpu.global.b32 %0, [%1];" : "=r"(v) : "l"(p) : "memory");
    return v;
}

__global__ void __launch_bounds__(TPB, 7)
scan_sweep(const float* __restrict__ x, float* __restrict__ out) {
    const int c   = blockIdx.x;          // chunk (predecessors have lower bid)
    const int dg  = blockIdx.y;          // channel half
    const int b   = blockIdx.z;          // batch
    const int tid = threadIdx.x;
    const int ch  = dg * DG + tid * 2;   // absolute channel base (owns 2)

    const float* base  = x   + ((size_t)b * T + (size_t)c * CH) * (3 * D) + ch;
    float*       obase = out + ((size_t)b * T + (size_t)c * CH) * D + ch;

    // Double-buffered register tiles for the 3 streams.
    float2 V[2][S], G[2][S], O[2][S];

    // ---- Prologue: issue subtile 0 loads (in flight during the lookback) --
#pragma unroll
    for (int t = 0; t < S; ++t) {
        const size_t row = (size_t)t * (3 * D);
        V[0][t] = __ldcs((const float2*)(base + row));
        G[0][t] = __ldcs((const float2*)(base + row + D));
        O[0][t] = __ldcs((const float2*)(base + row + 2 * D));
    }

    // ---- Prefix first: wait for predecessor's published inclusive prefix --
    float h0 = 0.f, h1 = 0.f;
    if (c > 0) {
        const int fidx = ((b * NDG + dg) * NC + (c - 1)) * TPB + tid;
        while (ld_acquire(&g_flag[fidx]) != FLG_PREF) { }
        const float2 pv = __ldcg((const float2*)&g_prefh[((size_t)b * NC + (c - 1)) * D + ch]);
        h0 = pv.x; h1 = pv.y;
    }

    // ---- Single pipelined sweep: load subtile s+1, compute+emit subtile s -
#pragma unroll
    for (int s = 0; s < NS; ++s) {
        const int cur = s & 1;
        const int nxt = cur ^ 1;

        if (s + 1 < NS) {
#pragma unroll
            for (int t = 0; t < S; ++t) {
                const size_t row = (size_t)((s + 1) * S + t) * (3 * D);
                V[nxt][t] = __ldcs((const float2*)(base + row));
                G[nxt][t] = __ldcs((const float2*)(base + row + D));
                O[nxt][t] = __ldcs((const float2*)(base + row + 2 * D));
            }
        }

#pragma unroll
        for (int t = 0; t < S; ++t) {
            const float2 vi = V[cur][t];
            const float2 gi = G[cur][t];
            const float2 go = O[cur][t];

            float i0 = sigm(gi.x), i1 = sigm(gi.y);
            float f0 = 1.f - i0,   f1 = 1.f - i1;
            float w0 = i0 * tanha(vi.x), w1 = i1 * tanha(vi.y);

            h0 = fmaf(f0, h0, w0);
            h1 = fmaf(f1, h1, w1);

            float2 o2;
            o2.x = tanha(h0) * sigm(go.x);
            o2.y = tanha(h1) * sigm(go.y);
            __stcs((float2*)(obase + (size_t)(s * S + t) * D), o2);
        }
    }

    // ---- Publish inclusive prefix for successors ---------------------------
    __stcg((float2*)&g_prefh[((size_t)b * NC + c) * D + ch], make_float2(h0, h1));
    st_release(&g_flag[((b * NDG + dg) * NC + c) * TPB + tid], FLG_PREF);
}

extern "C" void kernel_launch(void* const* d_in, const int* in_sizes, int n_in,
                              void* d_out, int out_size) {
    const float* x = (const float*)d_in[0];
    float* out = (float*)d_out;

    dim3 grid(NC, NDG, B);   // 256 x 2 x 4 = 2048 blocks
    scan_sweep<<<grid, TPB>>>(x, out);
}

// round 15
// speedup vs baseline: 1.5313x; 1.0007x over previous
#include <cuda_runtime.h>

// Problem shape
#define B    4
#define T    8192
#define D    512
#define CH   64                // time steps per chunk (per block)
#define S    4                 // subtile steps (pipeline stage)
#define NS   (CH / S)          // 16 subtiles
#define NC   (T / CH)          // 128 chunks per sequence
#define TPB  128               // threads per block
#define NDG  2                 // D-groups (channel halves) per chunk
#define DG   (D / NDG)         // 256 channels per block

// Flag states
#define FLG_NONE 0
#define FLG_PREF 2

// Scratch (device globals; zero-initialized at module load).
__device__ float g_prefh[B * NC * D];             // per-chunk inclusive-prefix h
__device__ int   g_flag [B * NDG * NC * TPB];     // per-(b, dgroup, chunk, thread)

__device__ __forceinline__ float tanha(float x) {
    float y;
    asm("tanh.approx.f32 %0, %1;" : "=f"(y) : "f"(x));
    return y;
}
__device__ __forceinline__ float sigm(float x) {
    return fmaf(tanha(0.5f * x), 0.5f, 0.5f);
}
__device__ __forceinline__ void st_release(int* p, int v) {
    asm volatile("st.release.gpu.global.b32 [%0], %1;" :: "l"(p), "r"(v) : "memory");
}
__device__ __forceinline__ int ld_acquire(const int* p) {
    int v;
    asm volatile("ld.acquire.gpu.global.b32 %0, [%1];" : "=r"(v) : "l"(p) : "memory");
    return v;
}

__global__ void __launch_bounds__(TPB, 7)
scan_sweep(const float* __restrict__ x, float* __restrict__ out) {
    const int c   = blockIdx.x;          // chunk (predecessors have lower bid)
    const int dg  = blockIdx.y;          // channel half
    const int b   = blockIdx.z;          // batch
    const int tid = threadIdx.x;
    const int ch  = dg * DG + tid * 2;   // absolute channel base (owns 2)

    const float* base  = x   + ((size_t)b * T + (size_t)c * CH) * (3 * D) + ch;
    float*       obase = out + ((size_t)b * T + (size_t)c * CH) * D + ch;

    // Double-buffered register tiles for the 3 streams.
    float2 V[2][S], G[2][S], O[2][S];

    // ---- Prologue: issue subtile 0 loads (in flight during the lookback) --
#pragma unroll
    for (int t = 0; t < S; ++t) {
        const size_t row = (size_t)t * (3 * D);
        V[0][t] = __ldcs((const float2*)(base + row));
        G[0][t] = __ldcs((const float2*)(base + row + D));
        O[0][t] = __ldcs((const float2*)(base + row + 2 * D));
    }

    // ---- Prefix first: wait for predecessor's published inclusive prefix --
    float h0 = 0.f, h1 = 0.f;
    if (c > 0) {
        const int fidx = ((b * NDG + dg) * NC + (c - 1)) * TPB + tid;
        while (ld_acquire(&g_flag[fidx]) != FLG_PREF) { }
        const float2 pv = __ldcg((const float2*)&g_prefh[((size_t)b * NC + (c - 1)) * D + ch]);
        h0 = pv.x; h1 = pv.y;
    }

    // ---- Single pipelined sweep: load subtile s+1, compute+emit subtile s -
#pragma unroll
    for (int s = 0; s < NS; ++s) {
        const int cur = s & 1;
        const int nxt = cur ^ 1;

        if (s + 1 < NS) {
#pragma unroll
            for (int t = 0; t < S; ++t) {
                const size_t row = (size_t)((s + 1) * S + t) * (3 * D);
                V[nxt][t] = __ldcs((const float2*)(base + row));
                G[nxt][t] = __ldcs((const float2*)(base + row + D));
                O[nxt][t] = __ldcs((const float2*)(base + row + 2 * D));
            }
        }

#pragma unroll
        for (int t = 0; t < S; ++t) {
            const float2 vi = V[cur][t];
            const float2 gi = G[cur][t];
            const float2 go = O[cur][t];

            float i0 = sigm(gi.x), i1 = sigm(gi.y);
            float f0 = 1.f - i0,   f1 = 1.f - i1;
            float w0 = i0 * tanha(vi.x), w1 = i1 * tanha(vi.y);

            h0 = fmaf(f0, h0, w0);
            h1 = fmaf(f1, h1, w1);

            float2 o2;
            o2.x = tanha(h0) * sigm(go.x);
            o2.y = tanha(h1) * sigm(go.y);
            __stcs((float2*)(obase + (size_t)(s * S + t) * D), o2);
        }
    }

    // ---- Publish inclusive prefix for successors ---------------------------
    __stcg((float2*)&g_prefh[((size_t)b * NC + c) * D + ch], make_float2(h0, h1));
    st_release(&g_flag[((b * NDG + dg) * NC + c) * TPB + tid], FLG_PREF);
}

extern "C" void kernel_launch(void* const* d_in, const int* in_sizes, int n_in,
                              void* d_out, int out_size) {
    const float* x = (const float*)d_in[0];
    float* out = (float*)d_out;

    dim3 grid(NC, NDG, B);   // 128 x 2 x 4 = 1024 blocks -> single wave
    scan_sweep<<<grid, TPB>>>(x, out);
}